// round 3
// baseline (speedup 1.0000x reference)
#include <cuda_runtime.h>
#include <cstdint>

#define BB   16
#define CC   128
#define HH   28
#define WW   28
#define FF   128
#define KK   1152      // CC*9
#define LL   784       // 28*28
#define LPAD 832       // 13*64
#define FT   64
#define LT   64
#define KC   32
#define NKC  (KK/KC)   // 36

// Scratch (allocation-free rule: __device__ globals)
__device__ __align__(16) float g_Pneg[(size_t)BB * KK * LPAD];  // -patches, zero padded
__device__ __align__(16) float g_Wt2[KK * 2 * FF];              // W transposed+duplicated: [K][2F], w stored twice

// ---------------- im2col (negated), cheap indexing ----------------
// grid: (x = 208 lp4 via threads, y = KK, z = BB); block 256 (threads 0..207 active)
__global__ void __launch_bounds__(256) im2col_kernel(const float* __restrict__ x) {
    const int lp4 = threadIdx.x;
    if (lp4 >= LPAD / 4) return;
    const int k = blockIdx.y;           // uniform
    const int b = blockIdx.z;           // uniform
    const int c  = k / 9;               // uniform per block
    const int r  = k - c * 9;
    const int kh = r / 3, kw = r - kh * 3;

    const float* xp = x + ((size_t)(b * CC + c)) * (HH * WW);

    float4 v = make_float4(0.f, 0.f, 0.f, 0.f);
    const int l0 = lp4 * 4;
    if (l0 < LL) {                      // whole float4 in-range or fully pad (LL%4==0)
        const int oh  = lp4 / 7;        // 28/4 = 7 float4 per image row
        const int ow0 = (lp4 - oh * 7) * 4;
        const int ih  = oh + kh - 1;
        if (ih >= 0 && ih < HH) {
            const float* row = xp + ih * WW;
            const int iw0 = ow0 + kw - 1;
            float* vv = reinterpret_cast<float*>(&v);
#pragma unroll
            for (int j = 0; j < 4; j++) {
                int iw = iw0 + j;
                if (iw >= 0 && iw < WW) vv[j] = -row[iw];
            }
        }
    }
    *reinterpret_cast<float4*>(&g_Pneg[((size_t)(b * KK + k)) * LPAD + l0]) = v;
}

// ---------------- W transpose + duplicate ----------------
__global__ void wtrans_kernel(const float* __restrict__ Wg) {
    int idx = blockIdx.x * blockDim.x + threadIdx.x;
    if (idx >= FF * KK) return;
    int k = idx % KK, f = idx / KK;
    float w = Wg[f * KK + k];
    float2 d = make_float2(w, w);
    *reinterpret_cast<float2*>(&g_Wt2[(size_t)k * (2 * FF) + 2 * f]) = d;
}

// ---------------- packed f32x2 helpers ----------------
__device__ __forceinline__ unsigned long long add2(unsigned long long a, unsigned long long b) {
    unsigned long long r;
    asm("add.rn.f32x2 %0, %1, %2;" : "=l"(r) : "l"(a), "l"(b));
    return r;
}
__device__ __forceinline__ void unpack2(unsigned long long v, float& lo, float& hi) {
    unsigned int a, b;
    asm("mov.b64 {%0, %1}, %2;" : "=r"(a), "=r"(b) : "l"(v));
    lo = __uint_as_float(a);
    hi = __uint_as_float(b);
}

#define CPA16(s, g) asm volatile("cp.async.ca.shared.global [%0], [%1], 16;\n" :: "r"(s), "l"(g))

// ---------------- main L1-distance kernel ----------------
// sW holds duplicated W: [KC][2*FT] floats; sP: [KC][LT]
__global__ void __launch_bounds__(256) adder_kernel(float* __restrict__ out) {
    __shared__ __align__(16) float sW[2][KC][2 * FT];
    __shared__ __align__(16) float sP[2][KC][LT];

    const int tid = threadIdx.x;
    const int b  = blockIdx.z;
    const int f0 = blockIdx.y * FT;
    const int l0 = blockIdx.x * LT;

    const float* gW = g_Wt2 + 2 * f0;                       // [K][2F] slice
    const float* gP = g_Pneg + (size_t)b * KK * LPAD;       // [K][LPAD]

    const uint32_t sW_base = (uint32_t)__cvta_generic_to_shared(&sW[0][0][0]);
    const uint32_t sP_base = (uint32_t)__cvta_generic_to_shared(&sP[0][0][0]);

    // fill mapping:
    // W tile: 32 rows x 128 floats = 32 float4 per row. thread -> row = tid>>3, 4 float4 at cols ((tid&7)*4 + j)
    // P tile: 32 rows x 64 floats = 16 float4 per row. thread -> row = tid>>3, 2 float4 at cols ((tid&7)*2 + j)
    const int fr  = tid >> 3;            // 0..31
    const int fc  = tid & 7;             // 0..7

    auto fill = [&](int s) {
        int buf = s & 1;
        int k0 = s * KC;
        const float* wrow = gW + (size_t)(k0 + fr) * (2 * FF);
        uint32_t wdst = sW_base + (uint32_t)((buf * KC + fr) * (2 * FT) * 4);
#pragma unroll
        for (int j = 0; j < 4; j++) {
            int col = (fc * 4 + j) * 4;  // float index
            CPA16(wdst + col * 4, wrow + col);
        }
        const float* prow = gP + (size_t)(k0 + fr) * LPAD + l0;
        uint32_t pdst = sP_base + (uint32_t)((buf * KC + fr) * LT * 4);
#pragma unroll
        for (int j = 0; j < 2; j++) {
            int col = (fc * 2 + j) * 4;
            CPA16(pdst + col * 4, prow + col);
        }
        asm volatile("cp.async.commit_group;\n" ::: "memory");
    };

    const int tf = (tid & 15) * 4;   // 4 consecutive f within tile
    const int tl = (tid >> 4) * 4;   // 4 consecutive l within tile

    unsigned long long acc[4][2];
#pragma unroll
    for (int i = 0; i < 4; i++) { acc[i][0] = 0ULL; acc[i][1] = 0ULL; }

    const unsigned long long ABSM = 0x7FFFFFFF7FFFFFFFULL;

    fill(0);
    for (int s = 0; s < NKC; s++) {
        asm volatile("cp.async.wait_group 0;\n" ::: "memory");
        __syncthreads();
        if (s + 1 < NKC) fill(s + 1);
        const int buf = s & 1;
#pragma unroll
        for (int kc = 0; kc < KC; kc++) {
            // duplicated W: (w,w) pairs directly as u64
            ulonglong2 wA = *reinterpret_cast<const ulonglong2*>(&sW[buf][kc][2 * tf]);      // (w0,w0),(w1,w1)
            ulonglong2 wB = *reinterpret_cast<const ulonglong2*>(&sW[buf][kc][2 * tf + 4]);  // (w2,w2),(w3,w3)
            ulonglong2 pv = *reinterpret_cast<const ulonglong2*>(&sP[buf][kc][tl]);          // (p0,p1),(p2,p3) negated
            unsigned long long w2[4] = {wA.x, wA.y, wB.x, wB.y};
#pragma unroll
            for (int i = 0; i < 4; i++) {
                unsigned long long d0 = add2(w2[i], pv.x) & ABSM;   // |w - p| packed
                unsigned long long d1 = add2(w2[i], pv.y) & ABSM;
                acc[i][0] = add2(acc[i][0], d0);
                acc[i][1] = add2(acc[i][1], d1);
            }
        }
    }

    // epilogue: out = -sum
    const int lbase = l0 + tl;
    if (lbase < LL) {   // LL % 4 == 0 -> whole float4 valid or invalid
#pragma unroll
        for (int i = 0; i < 4; i++) {
            float a0, a1, a2, a3;
            unpack2(acc[i][0], a0, a1);
            unpack2(acc[i][1], a2, a3);
            float4 v = make_float4(-a0, -a1, -a2, -a3);
            int f = f0 + tf + i;
            *reinterpret_cast<float4*>(&out[((size_t)(b * FF + f)) * LL + lbase]) = v;
        }
    }
}

extern "C" void kernel_launch(void* const* d_in, const int* in_sizes, int n_in,
                              void* d_out, int out_size) {
    const float* x  = (const float*)d_in[0];   // [16,128,28,28]
    const float* Wg = (const float*)d_in[1];   // [128,128,3,3]
    float* out = (float*)d_out;                // [16,128,28,28]

    dim3 g1(1, KK, BB);
    im2col_kernel<<<g1, 256>>>(x);
    wtrans_kernel<<<(FF * KK + 255) / 256, 256>>>(Wg);

    dim3 grid(LPAD / LT /*13*/, FF / FT /*2*/, BB /*16*/);
    adder_kernel<<<grid, 256>>>(out);
}

// round 4
// speedup vs baseline: 1.5717x; 1.5717x over previous
#include <cuda_runtime.h>
#include <cstdint>

#define BB   16
#define CC   128
#define HH   28
#define WW   28
#define FF   128
#define KK   1152      // CC*9
#define LL   784       // 28*28
#define LPAD 832       // 13*64
#define FT   64
#define LT   64
#define KC   32
#define NKC  (KK/KC)   // 36

// Scratch (allocation-free rule: __device__ globals)
__device__ __align__(16) float g_Pneg[(size_t)BB * KK * LPAD];  // -patches, zero padded
__device__ __align__(16) float g_Wt[KK * FF];                   // W transposed [K][F]

// ---------------- im2col (negated), all threads active ----------------
// grid (13, 72, 16), block (16,16): lp4 = bx*16+tx (0..207), k = by*16+ty (0..1151)
__global__ void __launch_bounds__(256) im2col_kernel(const float* __restrict__ x) {
    const int lp4 = blockIdx.x * 16 + threadIdx.x;
    const int k   = blockIdx.y * 16 + threadIdx.y;
    const int b   = blockIdx.z;
    const int c  = k / 9;
    const int r  = k - c * 9;
    const int kh = r / 3, kw = r - kh * 3;

    const float* xp = x + ((size_t)(b * CC + c)) * (HH * WW);

    float4 v = make_float4(0.f, 0.f, 0.f, 0.f);
    const int l0 = lp4 * 4;
    if (l0 < LL) {                      // whole float4 in-range or fully pad (LL%4==0)
        const int oh  = lp4 / 7;        // 7 float4 per 28-wide image row
        const int ow0 = (lp4 - oh * 7) * 4;
        const int ih  = oh + kh - 1;
        if (ih >= 0 && ih < HH) {
            const float* row = xp + ih * WW;
            const int iw0 = ow0 + kw - 1;
            float* vv = reinterpret_cast<float*>(&v);
#pragma unroll
            for (int j = 0; j < 4; j++) {
                int iw = iw0 + j;
                if (iw >= 0 && iw < WW) vv[j] = -row[iw];
            }
        }
    }
    *reinterpret_cast<float4*>(&g_Pneg[((size_t)(b * KK + k)) * LPAD + l0]) = v;
}

// ---------------- W transpose ----------------
__global__ void wtrans_kernel(const float* __restrict__ Wg) {
    int idx = blockIdx.x * blockDim.x + threadIdx.x;
    if (idx >= FF * KK) return;
    int k = idx % KK, f = idx / KK;
    g_Wt[k * FF + f] = Wg[f * KK + k];
}

// ---------------- packed f32x2 helpers ----------------
__device__ __forceinline__ unsigned long long add2(unsigned long long a, unsigned long long b) {
    unsigned long long r;
    asm("add.rn.f32x2 %0, %1, %2;" : "=l"(r) : "l"(a), "l"(b));
    return r;
}
__device__ __forceinline__ void unpack2(unsigned long long v, float& lo, float& hi) {
    unsigned int a, b;
    asm("mov.b64 {%0, %1}, %2;" : "=r"(a), "=r"(b) : "l"(v));
    lo = __uint_as_float(a);
    hi = __uint_as_float(b);
}

#define CPA16(s, g) asm volatile("cp.async.ca.shared.global [%0], [%1], 16;\n" :: "r"(s), "l"(g))

// ---------------- main L1-distance kernel ----------------
// sW: [KC][FT] plain (packed (w0,w1) read directly, 16B lane stride, conflict-free)
// sPd: [KC][2*LT] duplicated (p,p) pairs (read is warp-broadcast, conflict-free)
__global__ void __launch_bounds__(256) adder_kernel(float* __restrict__ out) {
    __shared__ __align__(16) float sW[2][KC][FT];        // 16 KB
    __shared__ __align__(16) float sPd[2][KC][2 * LT];   // 32 KB

    const int tid = threadIdx.x;
    const int b  = blockIdx.z;
    const int f0 = blockIdx.y * FT;
    const int l0 = blockIdx.x * LT;

    const float* gW = g_Wt + f0;                              // [K][FF] slice
    const float* gP = g_Pneg + (size_t)b * KK * LPAD + l0;    // [K][LPAD] slice

    const uint32_t sW_base = (uint32_t)__cvta_generic_to_shared(&sW[0][0][0]);

    // W fill: thread -> row = tid>>3 (0..31), 2 float4 at float cols (tid&7)*8 + {0,4}
    const int wrow = tid >> 3;
    const int wcol = (tid & 7) * 8;

    // P ldg/dup: m = tid&31 -> p float pair [2m, 2m+1] of rows {tid>>5 + 8i}
    const int pm = (tid & 31) * 2;     // p float index (even)
    const int pr = tid >> 5;           // base row 0..7

    float2 preg[4];
    auto ldgP = [&](int s) {
        const float* base = gP + (size_t)s * KC * LPAD;
#pragma unroll
        for (int i = 0; i < 4; i++)
            preg[i] = *reinterpret_cast<const float2*>(&base[(size_t)(pr + 8 * i) * LPAD + pm]);
    };
    auto stsP = [&](int s) {
        int buf = s & 1;
#pragma unroll
        for (int i = 0; i < 4; i++) {
            float4 d = make_float4(preg[i].x, preg[i].x, preg[i].y, preg[i].y);
            *reinterpret_cast<float4*>(&sPd[buf][pr + 8 * i][2 * pm]) = d;
        }
    };
    auto fillW = [&](int s) {
        int buf = s & 1;
        int k0 = s * KC;
        const float* wr = gW + (size_t)(k0 + wrow) * FF + wcol;
        uint32_t dst = sW_base + (uint32_t)(((buf * KC + wrow) * FT + wcol) * 4);
        CPA16(dst, wr);
        CPA16(dst + 16, wr + 4);
        asm volatile("cp.async.commit_group;\n" ::: "memory");
    };

    const int tf = (tid & 15) * 4;   // 4 consecutive f within tile (pairs come packed)
    const int tl = (tid >> 4) * 4;   // 4 consecutive l within tile (warp-broadcast reads)

    unsigned long long acc[4][2];    // acc[l][fpair]
#pragma unroll
    for (int i = 0; i < 4; i++) { acc[i][0] = 0ULL; acc[i][1] = 0ULL; }

    const unsigned long long ABSM = 0x7FFFFFFF7FFFFFFFULL;

    ldgP(0);
    fillW(0);
    for (int s = 0; s < NKC; s++) {
        const int buf = s & 1;
        stsP(s);
        asm volatile("cp.async.wait_group 0;\n" ::: "memory");
        __syncthreads();
        if (s + 1 < NKC) { ldgP(s + 1); fillW(s + 1); }
#pragma unroll
        for (int kc = 0; kc < KC; kc++) {
            ulonglong2 w  = *reinterpret_cast<const ulonglong2*>(&sW[buf][kc][tf]);        // (w0,w1),(w2,w3)
            ulonglong2 pA = *reinterpret_cast<const ulonglong2*>(&sPd[buf][kc][2 * tl]);   // (p0,p0),(p1,p1)
            ulonglong2 pB = *reinterpret_cast<const ulonglong2*>(&sPd[buf][kc][2 * tl + 4]); // (p2,p2),(p3,p3)
            unsigned long long pd[4] = {pA.x, pA.y, pB.x, pB.y};
#pragma unroll
            for (int l = 0; l < 4; l++) {
                unsigned long long d0 = add2(w.x, pd[l]) & ABSM;   // |w - p| packed over f
                unsigned long long d1 = add2(w.y, pd[l]) & ABSM;
                acc[l][0] = add2(acc[l][0], d0);
                acc[l][1] = add2(acc[l][1], d1);
            }
        }
    }

    // epilogue: out = -sum ; acc grouped by l with f pairs -> transpose in regs
    const int lbase = l0 + tl;
    if (lbase < LL) {   // LL % 4 == 0 -> whole float4 row segment valid or invalid
        float sums[4][4];  // [fi][l]
#pragma unroll
        for (int l = 0; l < 4; l++) {
            unpack2(acc[l][0], sums[0][l], sums[1][l]);
            unpack2(acc[l][1], sums[2][l], sums[3][l]);
        }
#pragma unroll
        for (int fi = 0; fi < 4; fi++) {
            float4 v = make_float4(-sums[fi][0], -sums[fi][1], -sums[fi][2], -sums[fi][3]);
            int f = f0 + tf + fi;
            *reinterpret_cast<float4*>(&out[((size_t)(b * FF + f)) * LL + lbase]) = v;
        }
    }
}

extern "C" void kernel_launch(void* const* d_in, const int* in_sizes, int n_in,
                              void* d_out, int out_size) {
    const float* x  = (const float*)d_in[0];   // [16,128,28,28]
    const float* Wg = (const float*)d_in[1];   // [128,128,3,3]
    float* out = (float*)d_out;                // [16,128,28,28]

    dim3 g1(13, 72, 16);
    dim3 b1(16, 16, 1);
    im2col_kernel<<<g1, b1>>>(x);
    wtrans_kernel<<<(FF * KK + 255) / 256, 256>>>(Wg);

    dim3 grid(LPAD / LT /*13*/, FF / FT /*2*/, BB /*16*/);
    adder_kernel<<<grid, 256>>>(out);
}

// round 5
// speedup vs baseline: 1.7182x; 1.0932x over previous
#include <cuda_runtime.h>
#include <cstdint>

#define BB   16
#define CC   128
#define HH   28
#define WW   28
#define FF   128
#define KK   1152      // CC*9
#define LL   784       // 28*28
#define LPAD 832       // 13*64
#define FT   64
#define LT   64
#define KC   32
#define NKC  (KK/KC)   // 36
#define NST  3         // pipeline stages

// Scratch (allocation-free rule: __device__ globals)
__device__ __align__(16) float g_Pneg[(size_t)BB * KK * LPAD];  // -patches, zero padded
__device__ __align__(16) float g_Wt[KK * FF];                   // W transposed [K][F]

// ---------------- im2col (negated), all threads active ----------------
// grid (13, 72, 16), block (16,16): lp4 = bx*16+tx (0..207), k = by*16+ty (0..1151)
__global__ void __launch_bounds__(256) im2col_kernel(const float* __restrict__ x) {
    const int lp4 = blockIdx.x * 16 + threadIdx.x;
    const int k   = blockIdx.y * 16 + threadIdx.y;
    const int b   = blockIdx.z;
    const int c  = k / 9;
    const int r  = k - c * 9;
    const int kh = r / 3, kw = r - kh * 3;

    const float* xp = x + ((size_t)(b * CC + c)) * (HH * WW);

    float4 v = make_float4(0.f, 0.f, 0.f, 0.f);
    const int l0 = lp4 * 4;
    if (l0 < LL) {                      // whole float4 in-range or fully pad (LL%4==0)
        const int oh  = lp4 / 7;        // 7 float4 per 28-wide image row
        const int ow0 = (lp4 - oh * 7) * 4;
        const int ih  = oh + kh - 1;
        if (ih >= 0 && ih < HH) {
            const float* row = xp + ih * WW;
            const int iw0 = ow0 + kw - 1;
            float* vv = reinterpret_cast<float*>(&v);
#pragma unroll
            for (int j = 0; j < 4; j++) {
                int iw = iw0 + j;
                if (iw >= 0 && iw < WW) vv[j] = -row[iw];
            }
        }
    }
    *reinterpret_cast<float4*>(&g_Pneg[((size_t)(b * KK + k)) * LPAD + l0]) = v;
}

// ---------------- W transpose ----------------
__global__ void wtrans_kernel(const float* __restrict__ Wg) {
    int idx = blockIdx.x * blockDim.x + threadIdx.x;
    if (idx >= FF * KK) return;
    int k = idx % KK, f = idx / KK;
    g_Wt[k * FF + f] = Wg[f * KK + k];
}

// ---------------- packed f32x2 helpers ----------------
__device__ __forceinline__ unsigned long long add2(unsigned long long a, unsigned long long b) {
    unsigned long long r;
    asm("add.rn.f32x2 %0, %1, %2;" : "=l"(r) : "l"(a), "l"(b));
    return r;
}
__device__ __forceinline__ unsigned long long pack2(float lo, float hi) {
    unsigned long long r;
    asm("mov.b64 %0, {%1, %2};" : "=l"(r) : "r"(__float_as_uint(lo)), "r"(__float_as_uint(hi)));
    return r;
}
__device__ __forceinline__ void unpack2(unsigned long long v, float& lo, float& hi) {
    unsigned int a, b;
    asm("mov.b64 {%0, %1}, %2;" : "=r"(a), "=r"(b) : "l"(v));
    lo = __uint_as_float(a);
    hi = __uint_as_float(b);
}

#define CPA16(s, g) asm volatile("cp.async.cg.shared.global [%0], [%1], 16;\n" :: "r"(s), "l"(g))

// ---------------- main L1-distance kernel ----------------
// 3-stage cp.async pipeline. sW/sP: [NST][KC][64].
__global__ void __launch_bounds__(256) adder_kernel(float* __restrict__ out) {
    __shared__ __align__(16) float sW[NST][KC][FT];   // 24 KB
    __shared__ __align__(16) float sP[NST][KC][LT];   // 24 KB

    const int tid = threadIdx.x;
    const int b  = blockIdx.z;
    const int f0 = blockIdx.y * FT;
    const int l0 = blockIdx.x * LT;

    const float* gW = g_Wt + f0;                             // [K][FF] slice
    const float* gP = g_Pneg + (size_t)b * KK * LPAD + l0;   // [K][LPAD] slice

    const uint32_t sW_base = (uint32_t)__cvta_generic_to_shared(&sW[0][0][0]);
    const uint32_t sP_base = (uint32_t)__cvta_generic_to_shared(&sP[0][0][0]);

    // fill mapping: per stage each tile = 32 rows x 64 floats = 512 float4;
    // each thread copies 2 float4 of W and 2 of P.
    const int fr0 = tid >> 4;            // 0..15
    const int fr1 = fr0 + 16;            // 16..31
    const int fc  = (tid & 15) * 4;      // float col 0..60

    auto fill = [&](int s, int buf) {
        int k0 = s * KC;
        uint32_t dW0 = sW_base + (uint32_t)(((buf * KC + fr0) * FT + fc) * 4);
        uint32_t dW1 = sW_base + (uint32_t)(((buf * KC + fr1) * FT + fc) * 4);
        CPA16(dW0, gW + (size_t)(k0 + fr0) * FF + fc);
        CPA16(dW1, gW + (size_t)(k0 + fr1) * FF + fc);
        uint32_t dP0 = sP_base + (uint32_t)(((buf * KC + fr0) * LT + fc) * 4);
        uint32_t dP1 = sP_base + (uint32_t)(((buf * KC + fr1) * LT + fc) * 4);
        CPA16(dP0, gP + (size_t)(k0 + fr0) * LPAD + fc);
        CPA16(dP1, gP + (size_t)(k0 + fr1) * LPAD + fc);
        asm volatile("cp.async.commit_group;\n" ::: "memory");
    };

    const int tf = (tid & 15) * 4;   // 4 consecutive f within tile
    const int tl = (tid >> 4) * 4;   // 4 consecutive l within tile

    unsigned long long acc[4][2];    // acc[f][lpair]
#pragma unroll
    for (int i = 0; i < 4; i++) { acc[i][0] = 0ULL; acc[i][1] = 0ULL; }

    const unsigned long long ABSM = 0x7FFFFFFF7FFFFFFFULL;

    fill(0, 0);
    fill(1, 1);
    int buf = 0;
    for (int s = 0; s < NKC; s++) {
        asm volatile("cp.async.wait_group 1;\n" ::: "memory");
        __syncthreads();
        // prefetch distance 2: writes buffer used 2 stages ahead (read at s-1, done)
        if (s + 2 < NKC) {
            int nbuf = buf + 2; if (nbuf >= NST) nbuf -= NST;
            fill(s + 2, nbuf);
        }
#pragma unroll
        for (int kc = 0; kc < KC; kc++) {
            float4 wv = *reinterpret_cast<const float4*>(&sW[buf][kc][tf]);
            ulonglong2 pv = *reinterpret_cast<const ulonglong2*>(&sP[buf][kc][tl]); // (p0,p1),(p2,p3) negated
            float wvv[4] = {wv.x, wv.y, wv.z, wv.w};
#pragma unroll
            for (int i = 0; i < 4; i++) {
                unsigned long long w2 = pack2(wvv[i], wvv[i]);
                unsigned long long d0 = add2(w2, pv.x) & ABSM;   // |w - p| packed over l
                unsigned long long d1 = add2(w2, pv.y) & ABSM;
                acc[i][0] = add2(acc[i][0], d0);
                acc[i][1] = add2(acc[i][1], d1);
            }
        }
        buf = buf + 1 == NST ? 0 : buf + 1;
    }

    // epilogue: out = -sum
    const int lbase = l0 + tl;
    if (lbase < LL) {   // LL % 4 == 0 -> whole float4 valid or invalid
#pragma unroll
        for (int i = 0; i < 4; i++) {
            float a0, a1, a2, a3;
            unpack2(acc[i][0], a0, a1);
            unpack2(acc[i][1], a2, a3);
            float4 v = make_float4(-a0, -a1, -a2, -a3);
            int f = f0 + tf + i;
            *reinterpret_cast<float4*>(&out[((size_t)(b * FF + f)) * LL + lbase]) = v;
        }
    }
}

extern "C" void kernel_launch(void* const* d_in, const int* in_sizes, int n_in,
                              void* d_out, int out_size) {
    const float* x  = (const float*)d_in[0];   // [16,128,28,28]
    const float* Wg = (const float*)d_in[1];   // [128,128,3,3]
    float* out = (float*)d_out;                // [16,128,28,28]

    dim3 g1(13, 72, 16);
    dim3 b1(16, 16, 1);
    im2col_kernel<<<g1, b1>>>(x);
    wtrans_kernel<<<(FF * KK + 255) / 256, 256>>>(Wg);

    dim3 grid(LPAD / LT /*13*/, FF / FT /*2*/, BB /*16*/);
    adder_kernel<<<grid, 256>>>(out);
}